// round 2
// baseline (speedup 1.0000x reference)
#include <cuda_runtime.h>
#include <cstdint>

#define V_N 65536
#define E_N 4096
#define P_N 4096
#define T_N 512
#define SENTF 1000000000.0f
#define BIGF  1e30f
#define INFF  __int_as_float(0x7f800000)

#define TPB 256
#define MAX_GRID 512

// Scratch (device globals: no allocations allowed)
__device__ float2 g_passA[E_N];   // (xmn, xmx)
__device__ float4 g_passB[E_N];   // (ymn, ymx, b, 1/a)
__device__ float2 g_ab[E_N];      // (a, b)
__device__ float4 g_tbl[T_N];     // TableR cols 3..6
__device__ float  g_m[P_N];
__device__ int    g_valid[P_N];

// Grid barrier state: monotonic counters, safe across graph replays.
__device__ unsigned g_arrive  = 0;
__device__ unsigned g_release = 0;

__device__ __forceinline__ void grid_barrier(int nblocks) {
    __syncthreads();
    if (threadIdx.x == 0) {
        __threadfence();
        unsigned ticket = atomicAdd(&g_arrive, 1u);
        unsigned gen = ticket / (unsigned)nblocks;
        if (ticket % (unsigned)nblocks == (unsigned)(nblocks - 1)) {
            atomicAdd(&g_release, 1u);           // release generation 'gen'
        } else {
            while (atomicAdd(&g_release, 0u) < gen + 1u) { }
        }
        __threadfence();
    }
    __syncthreads();
}

// ---------------------------------------------------------------------------
// Fused kernel: prep -> barrier -> points -> barrier -> scan (block 0)
// ---------------------------------------------------------------------------
__global__ void __launch_bounds__(TPB) fused_kernel(
        const float* __restrict__ verts,
        const float* __restrict__ tableR,
        const int*   __restrict__ edges,
        const int*   __restrict__ listAll,
        float*       __restrict__ out) {
    const unsigned FULL = 0xffffffffu;
    const int nblocks = gridDim.x;
    const int gtid = blockIdx.x * TPB + threadIdx.x;
    const int gthreads = nblocks * TPB;
    const int lane = threadIdx.x & 31;
    const int wid = threadIdx.x >> 5;

    // ================= Phase A: per-edge precompute + table =================
    for (int t = gtid; t < T_N; t += gthreads) {
        const float* r = tableR + t * 7;
        g_tbl[t] = make_float4(r[3], r[4], r[5], r[6]);
    }
    for (int e = gtid; e < E_N; e += gthreads) {
        int i0 = edges[2 * e + 0];
        int i1 = edges[2 * e + 1];
        float x0 = verts[3 * i0 + 0], y0 = verts[3 * i0 + 1];
        float x1 = verts[3 * i1 + 0], y1 = verts[3 * i1 + 1];
        float a = (y0 - y1) / (x0 - x1);                 // IEEE div (matches ref)
        float b = __fsub_rn(y0, __fmul_rn(a, x0));       // no FMA contraction
        g_passA[e] = make_float2(fminf(x0, x1), fmaxf(x0, x1));
        g_passB[e] = make_float4(fminf(y0, y1), fmaxf(y0, y1), b, 1.0f / a);
        g_ab[e]    = make_float2(a, b);
    }

    grid_barrier(nblocks);

    // ================= Phase B: warp-per-point =================
    const int warps_total = nblocks * (TPB / 32);
    for (int p = blockIdx.x * (TPB / 32) + wid; p < P_N; p += warps_total) {
        int li = __ldg(&listAll[p]);
        float px = __ldg(&verts[3 * li + 0]);
        float py = __ldg(&verts[3 * li + 1]);

        // ---- Pass 1: first edge index with px strictly inside (xmn, xmx) ----
        int idx = 0x7fffffff;
        for (int e = lane; e < E_N; e += 32) {
            float2 mm = __ldg(&g_passA[e]);
            if (px > mm.x && px < mm.y) { idx = e; break; }  // lane stream ascending
        }
        #pragma unroll
        for (int o = 16; o; o >>= 1)
            idx = min(idx, __shfl_xor_sync(FULL, idx, o));
        if (idx == 0x7fffffff) idx = E_N - 1;

        float2 ab = __ldg(&g_ab[idx]);
        float exposeY = __fadd_rn(__fmul_rn(ab.x, px), ab.y);  // no FMA contraction
        float L1 = fabsf(py - exposeY);
        float cy = (py + exposeY) * 0.5f;

        // ---- Pass 2: condB reductions over all edges ----
        int n = 0;
        float xallmx = -SENTF, xallmn = SENTF;
        float xs = SENTF, xinf = -SENTF;
        #pragma unroll 4
        for (int e = lane; e < E_N; e += 32) {
            float4 q = __ldg(&g_passB[e]);       // (ymn, ymx, b, inv_a)
            if (cy > q.x && cy < q.y) {
                float xi = __fmul_rn(__fsub_rn(cy, q.z), q.w);
                n++;
                xallmx = fmaxf(xallmx, xi);
                xallmn = fminf(xallmn, xi);
                if (xi >= px) xs   = fminf(xs,   xi);
                else          xinf = fmaxf(xinf, xi);
            }
        }
        #pragma unroll
        for (int o = 16; o; o >>= 1) {
            n      +=              __shfl_xor_sync(FULL, n,      o);
            xallmx = fmaxf(xallmx, __shfl_xor_sync(FULL, xallmx, o));
            xallmn = fminf(xallmn, __shfl_xor_sync(FULL, xallmn, o));
            xs     = fminf(xs,     __shfl_xor_sync(FULL, xs,     o));
            xinf   = fmaxf(xinf,   __shfl_xor_sync(FULL, xinf,   o));
        }

        // condB true => xi in [xmn,xmx] subset [0,1], so presence <=> sentinel moved
        int hs = xs   <  SENTF;
        int hi = xinf > -SENTF;
        int valid = (n == 2) || (n > 2 && hs && hi);
        float dx  = (n == 2) ? (xallmx - xallmn) : (xs - xinf);
        float L2  = fabsf(dx);
        float d1  = fabsf(cy - 1.0f);
        float d2  = fabsf(px - 1.0f);

        // ---- Table min over T=512 rows ----
        float pm = INFF;
        #pragma unroll 4
        for (int t = lane; t < T_N; t += 32) {
            float4 r = __ldg(&g_tbl[t]);
            float al = fabsf(L1 - r.x) + fabsf(L2 - r.y)
                     + fabsf(d1 - r.z) + fabsf(d2 - r.w);
            pm = fminf(pm, al);
        }
        #pragma unroll
        for (int o = 16; o; o >>= 1)
            pm = fminf(pm, __shfl_xor_sync(FULL, pm, o));

        if (lane == 0) {
            g_m[p]     = valid ? pm : BIGF;
            g_valid[p] = valid;
        }
    }

    grid_barrier(nblocks);

    // ================= Phase C: cummin + masked sum (block 0 only) ==========
    if (blockIdx.x != 0) return;
    {
        __shared__ float s_wtot[8];     // per-warp inclusive totals
        __shared__ float s_sum[8];
        const int tid = threadIdx.x;    // 256 threads, 16 values each
        const int base = tid * 16;

        // local inclusive cummin over 16 consecutive values
        float c[16];
        float run = INFF;
        #pragma unroll
        for (int i = 0; i < 16; i++) {
            run = fminf(run, g_m[base + i]);
            c[i] = run;
        }
        float tot = run;   // chunk min

        // warp inclusive min-scan of chunk minima
        float scan = tot;
        #pragma unroll
        for (int o = 1; o < 32; o <<= 1) {
            float v = __shfl_up_sync(FULL, scan, o);
            if (lane >= o) scan = fminf(scan, v);
        }
        if (lane == 31) s_wtot[wid] = scan;   // warp-inclusive total
        __syncthreads();

        // exclusive prefix of warp totals (8 warps — serial read, cheap)
        float wpre = INFF;
        for (int w = 0; w < 8; w++)
            if (w < wid) wpre = fminf(wpre, s_wtot[w]);

        // exclusive prefix for this thread's chunk
        float lpre = __shfl_up_sync(FULL, scan, 1);
        float pre = fminf(wpre, (lane == 0) ? INFF : lpre);

        // masked sum of running cummin
        float acc = 0.0f;
        #pragma unroll
        for (int i = 0; i < 16; i++) {
            if (g_valid[base + i]) acc += fminf(pre, c[i]);
        }

        // block sum: warp reduce + smem combine
        #pragma unroll
        for (int o = 16; o; o >>= 1)
            acc += __shfl_xor_sync(FULL, acc, o);
        if (lane == 0) s_sum[wid] = acc;
        __syncthreads();
        if (tid == 0) {
            float s = 0.0f;
            #pragma unroll
            for (int w = 0; w < 8; w++) s += s_sum[w];
            out[0] = s;
        }
    }
}

// ---------------------------------------------------------------------------
extern "C" void kernel_launch(void* const* d_in, const int* in_sizes, int n_in,
                              void* d_out, int out_size) {
    const float* verts   = (const float*)d_in[0];
    const float* tableR  = (const float*)d_in[1];
    const int*   edges   = (const int*)  d_in[2];
    const int*   listAll = (const int*)  d_in[3];

    int dev = 0;
    cudaGetDevice(&dev);
    int nsm = 0;
    cudaDeviceGetAttribute(&nsm, cudaDevAttrMultiProcessorCount, dev);
    int maxb = 0;
    cudaOccupancyMaxActiveBlocksPerMultiprocessor(&maxb, fused_kernel, TPB, 0);
    if (maxb < 1) maxb = 1;
    int grid = nsm * maxb;
    if (grid > MAX_GRID) grid = MAX_GRID;
    if (grid < 1) grid = 1;

    fused_kernel<<<grid, TPB>>>(verts, tableR, edges, listAll, (float*)d_out);
}